// round 1
// baseline (speedup 1.0000x reference)
#include <cuda_runtime.h>
#include <math.h>

#define DIMQ     1024
#define HEADS    16
#define DHEAD    64
#define SEQ      2048
#define BATCH    2
#define NTOK     (BATCH * SEQ)      // 4096
#define QKV_N    (3 * DIMQ)         // 3072
#define SCALE_A  0.125f             // 1/sqrt(64)

// Scratch (static device globals — allocation-free)
__device__ float g_qkv[(size_t)NTOK * QKV_N];  // [tok][3072]: Q | K | V
__device__ float g_att[(size_t)NTOK * DIMQ];   // [tok][1024] attention result (b n (h d))

// ---------------------------------------------------------------------------
// Classic 128x128x8 register-tiled SGEMM: C = A @ B (+ bias), row-major.
// 256 threads, each computes an 8x8 micro-tile.
// ---------------------------------------------------------------------------
__global__ void __launch_bounds__(256) sgemm128(
    const float* __restrict__ A, const float* __restrict__ B,
    const float* __restrict__ bias, float* __restrict__ C,
    int M, int N, int K)
{
    const int BK = 8;
    __shared__ float As[BK][128];
    __shared__ float Bs[BK][128];

    int tid = threadIdx.x;
    int tx = tid & 15;          // 0..15
    int ty = tid >> 4;          // 0..15
    long row0 = (long)blockIdx.y * 128;
    long col0 = (long)blockIdx.x * 128;

    const float* Ab = A + row0 * K;
    const float* Bb = B + col0;

    float acc[8][8];
    #pragma unroll
    for (int i = 0; i < 8; i++)
        #pragma unroll
        for (int j = 0; j < 8; j++) acc[i][j] = 0.f;

    int arow = tid >> 1;            // 0..127
    int acol = (tid & 1) * 4;       // 0 or 4
    int brow = tid >> 5;            // 0..7
    int bcol = (tid & 31) * 4;      // 0..124

    for (int k0 = 0; k0 < K; k0 += BK) {
        float4 a4 = *(const float4*)(Ab + (long)arow * K + k0 + acol);
        As[acol + 0][arow] = a4.x;
        As[acol + 1][arow] = a4.y;
        As[acol + 2][arow] = a4.z;
        As[acol + 3][arow] = a4.w;
        float4 b4 = *(const float4*)(Bb + (long)(k0 + brow) * N + bcol);
        *(float4*)&Bs[brow][bcol] = b4;
        __syncthreads();

        #pragma unroll
        for (int k = 0; k < BK; k++) {
            float a[8], bb[8];
            *(float4*)&a[0]  = *(const float4*)&As[k][ty * 8];
            *(float4*)&a[4]  = *(const float4*)&As[k][ty * 8 + 4];
            *(float4*)&bb[0] = *(const float4*)&Bs[k][tx * 8];
            *(float4*)&bb[4] = *(const float4*)&Bs[k][tx * 8 + 4];
            #pragma unroll
            for (int i = 0; i < 8; i++)
                #pragma unroll
                for (int j = 0; j < 8; j++)
                    acc[i][j] += a[i] * bb[j];
        }
        __syncthreads();
    }

    #pragma unroll
    for (int i = 0; i < 8; i++) {
        long r = row0 + ty * 8 + i;
        #pragma unroll
        for (int j = 0; j < 8; j += 4) {
            long c = col0 + tx * 8 + j;
            float4 v;
            v.x = acc[i][j + 0]; v.y = acc[i][j + 1];
            v.z = acc[i][j + 2]; v.w = acc[i][j + 3];
            if (bias) {
                v.x += bias[c + 0]; v.y += bias[c + 1];
                v.z += bias[c + 2]; v.w += bias[c + 3];
            }
            *(float4*)(C + r * N + c) = v;
        }
    }
}

// ---------------------------------------------------------------------------
// Flash attention, fp32. One CTA = 64 query rows of one (batch, head).
// Loops over 2048 keys in 64-wide tiles with online softmax.
// Thread layout 16x16; each thread owns a 4x4 tile of S and of O.
// ---------------------------------------------------------------------------
#define FA_SMEM_FLOATS (3 * 64 * 65 + 64 * 64)

__global__ void __launch_bounds__(256) flash_attn(
    const float* __restrict__ qkv, float* __restrict__ out)
{
    extern __shared__ float sm[];
    float (*Qs)[65] = (float(*)[65])(sm);              // [d][m], padded
    float (*Ks)[65] = (float(*)[65])(sm + 64 * 65);    // [d][n], padded
    float (*Ps)[65] = (float(*)[65])(sm + 2 * 64 * 65);// [n][m], padded
    float (*Vs)[64] = (float(*)[64])(sm + 3 * 64 * 65);// [n][c], natural

    int tid = threadIdx.x;
    int tx = tid & 15;
    int ty = tid >> 4;
    int h = blockIdx.y;
    int b = blockIdx.z;
    int q0 = blockIdx.x * 64;

    const size_t base = (size_t)b * SEQ * QKV_N;
    const float* qb = qkv + base + h * DHEAD;
    const float* kb = qkv + base + DIMQ + h * DHEAD;
    const float* vb = qkv + base + 2 * DIMQ + h * DHEAD;

    // Load Q tile (64 rows x 64 dims), transposed into Qs[d][m]
    {
        int r  = tid >> 4;          // 0..15
        int c4 = (tid & 15) << 2;   // 0..60
        #pragma unroll
        for (int it = 0; it < 4; it++) {
            int row = r + it * 16;
            float4 v = *(const float4*)(qb + (size_t)(q0 + row) * QKV_N + c4);
            Qs[c4 + 0][row] = v.x;
            Qs[c4 + 1][row] = v.y;
            Qs[c4 + 2][row] = v.z;
            Qs[c4 + 3][row] = v.w;
        }
    }

    float o[4][4];
    float mi[4], li[4];
    #pragma unroll
    for (int i = 0; i < 4; i++) {
        mi[i] = -1e30f; li[i] = 0.f;
        #pragma unroll
        for (int j = 0; j < 4; j++) o[i][j] = 0.f;
    }

    for (int kt = 0; kt < SEQ; kt += 64) {
        __syncthreads();  // protects Ks/Vs/Ps reuse (and first-iter Qs visibility)
        {
            int r  = tid >> 4;
            int c4 = (tid & 15) << 2;
            #pragma unroll
            for (int it = 0; it < 4; it++) {
                int row = r + it * 16;
                float4 kv = *(const float4*)(kb + (size_t)(kt + row) * QKV_N + c4);
                Ks[c4 + 0][row] = kv.x;
                Ks[c4 + 1][row] = kv.y;
                Ks[c4 + 2][row] = kv.z;
                Ks[c4 + 3][row] = kv.w;
                float4 vv = *(const float4*)(vb + (size_t)(kt + row) * QKV_N + c4);
                *(float4*)&Vs[row][c4] = vv;
            }
        }
        __syncthreads();

        // S = (Q K^T) * scale  — 64x64x64, 4x4 per thread
        float s[4][4];
        #pragma unroll
        for (int i = 0; i < 4; i++)
            #pragma unroll
            for (int j = 0; j < 4; j++) s[i][j] = 0.f;

        #pragma unroll 8
        for (int d = 0; d < 64; d++) {
            float a[4], bb[4];
            #pragma unroll
            for (int i = 0; i < 4; i++) a[i] = Qs[d][ty * 4 + i];
            #pragma unroll
            for (int j = 0; j < 4; j++) bb[j] = Ks[d][tx * 4 + j];
            #pragma unroll
            for (int i = 0; i < 4; i++)
                #pragma unroll
                for (int j = 0; j < 4; j++)
                    s[i][j] += a[i] * bb[j];
        }

        // Online softmax update (row stats via 16-lane shuffle reduce; the 16
        // tx-threads of a row group occupy one half-warp, so xor 1,2,4,8 stays
        // inside the group).
        #pragma unroll
        for (int i = 0; i < 4; i++) {
            #pragma unroll
            for (int j = 0; j < 4; j++) s[i][j] *= SCALE_A;

            float mx = fmaxf(fmaxf(s[i][0], s[i][1]), fmaxf(s[i][2], s[i][3]));
            #pragma unroll
            for (int off = 1; off < 16; off <<= 1)
                mx = fmaxf(mx, __shfl_xor_sync(0xffffffffu, mx, off));

            float mnew = fmaxf(mi[i], mx);
            float corr = __expf(mi[i] - mnew);
            mi[i] = mnew;

            float rs = 0.f;
            #pragma unroll
            for (int j = 0; j < 4; j++) {
                s[i][j] = __expf(s[i][j] - mnew);
                rs += s[i][j];
            }
            #pragma unroll
            for (int off = 1; off < 16; off <<= 1)
                rs += __shfl_xor_sync(0xffffffffu, rs, off);

            li[i] = li[i] * corr + rs;
            #pragma unroll
            for (int j = 0; j < 4; j++) {
                o[i][j] *= corr;
                Ps[tx * 4 + j][ty * 4 + i] = s[i][j];  // transposed, stride 65
            }
        }
        __syncthreads();

        // O += P @ V  — 64x64x64
        #pragma unroll 8
        for (int n = 0; n < 64; n++) {
            float a[4];
            #pragma unroll
            for (int i = 0; i < 4; i++) a[i] = Ps[n][ty * 4 + i];
            float4 bv = *(const float4*)&Vs[n][tx * 4];
            float bb[4] = {bv.x, bv.y, bv.z, bv.w};
            #pragma unroll
            for (int i = 0; i < 4; i++)
                #pragma unroll
                for (int j = 0; j < 4; j++)
                    o[i][j] += a[i] * bb[j];
        }
    }

    // Epilogue: normalize and store into (b, n, h*64+c) layout
    float* ob = out + ((size_t)b * SEQ + q0) * DIMQ + h * DHEAD;
    #pragma unroll
    for (int i = 0; i < 4; i++) {
        float inv = 1.f / li[i];
        float4 v;
        v.x = o[i][0] * inv; v.y = o[i][1] * inv;
        v.z = o[i][2] * inv; v.w = o[i][3] * inv;
        *(float4*)(ob + (size_t)(ty * 4 + i) * DIMQ + tx * 4) = v;
    }
}

// ---------------------------------------------------------------------------
// Launch
// ---------------------------------------------------------------------------
extern "C" void kernel_launch(void* const* d_in, const int* in_sizes, int n_in,
                              void* d_out, int out_size)
{
    const float* x    = (const float*)d_in[0];   // [2,2048,1024]
    const float* Wqkv = (const float*)d_in[1];   // [1024,3072]
    const float* Wout = (const float*)d_in[2];   // [1024,1024]
    const float* bout = (const float*)d_in[3];   // [1024]
    float* out = (float*)d_out;                  // [2,2048,1024]

    float* qkv = nullptr;
    float* att = nullptr;
    cudaGetSymbolAddress((void**)&qkv, g_qkv);
    cudaGetSymbolAddress((void**)&att, g_att);

    // Stage 1: qkv = x @ W_qkv        (4096 x 3072 x 1024)
    {
        dim3 grid(QKV_N / 128, NTOK / 128);
        sgemm128<<<grid, 256>>>(x, Wqkv, nullptr, qkv, NTOK, QKV_N, DIMQ);
    }

    // Stage 2: flash attention per (q-tile, head, batch)
    {
        int smem_bytes = FA_SMEM_FLOATS * (int)sizeof(float);   // 66304 B
        cudaFuncSetAttribute(flash_attn,
                             cudaFuncAttributeMaxDynamicSharedMemorySize,
                             smem_bytes);
        dim3 grid(SEQ / 64, HEADS, BATCH);
        flash_attn<<<grid, 256, smem_bytes>>>(qkv, att);
    }

    // Stage 3: out = att @ W_out + b_out   (4096 x 1024 x 1024)
    {
        dim3 grid(DIMQ / 128, NTOK / 128);
        sgemm128<<<grid, 256>>>(att, Wout, bout, out, NTOK, DIMQ, DIMQ);
    }
}

// round 2
// speedup vs baseline: 3.0413x; 3.0413x over previous
#include <cuda_runtime.h>
#include <math.h>
#include <stdint.h>

#define DIMQ     1024
#define HEADS    16
#define DHEAD    64
#define SEQ      2048
#define BATCH    2
#define NTOK     (BATCH * SEQ)      // 4096
#define QKV_N    (3 * DIMQ)         // 3072
#define SCALE_A  0.125f             // 1/sqrt(64)
#define LOG2E    1.4426950408889634f

// Scratch (static device globals — allocation-free)
__device__ float g_qkv[(size_t)NTOK * QKV_N];  // [tok][3072]: Q | K | V
__device__ float g_att[(size_t)NTOK * DIMQ];   // [tok][1024] attention result

// ---------------------------------------------------------------------------
// tf32 helpers
// ---------------------------------------------------------------------------
__device__ __forceinline__ uint32_t f2tf(float x) {
    uint32_t y;
    asm("cvt.rna.tf32.f32 %0, %1;" : "=r"(y) : "f"(x));
    return y;
}
__device__ __forceinline__ float tfbits(float x) {
    return __uint_as_float(f2tf(x));
}
__device__ __forceinline__ void mma_tf32(float* c, const uint32_t* a, const uint32_t* b) {
    asm volatile(
        "mma.sync.aligned.m16n8k8.row.col.f32.tf32.tf32.f32 "
        "{%0,%1,%2,%3},{%4,%5,%6,%7},{%8,%9},{%0,%1,%2,%3};"
        : "+f"(c[0]), "+f"(c[1]), "+f"(c[2]), "+f"(c[3])
        : "r"(a[0]), "r"(a[1]), "r"(a[2]), "r"(a[3]),
          "r"(b[0]), "r"(b[1]));
}

// ---------------------------------------------------------------------------
// tf32 tensor-core GEMM: C = A @ B (+bias). 128x128 tile, BK=16, 256 threads.
// Warp grid 4x2 (rows x cols): each warp computes 32x64 via m16n8k8 frags.
// As stored [k][m] (transposed), Bs [k][n]; stride 136 floats -> conflict-free
// fragment loads (bank = (8k + idx) mod 32, k in 0..3 disjoint octets).
// ---------------------------------------------------------------------------
#define GS 136

__global__ void __launch_bounds__(256) sgemm_tf32(
    const float* __restrict__ A, const float* __restrict__ B,
    const float* __restrict__ bias, float* __restrict__ C,
    int M, int N, int K)
{
    __shared__ float As[16][GS];
    __shared__ float Bs[16][GS];

    const int tid  = threadIdx.x;
    const int lane = tid & 31;
    const int wid  = tid >> 5;
    const int wm   = wid & 3;       // 0..3 -> 32-row slab
    const int wn   = wid >> 2;      // 0..1 -> 64-col slab
    const int lq   = lane >> 2;     // 0..7
    const int lr   = lane & 3;      // 0..3

    const long row0 = (long)blockIdx.y * 128;
    const long col0 = (long)blockIdx.x * 128;

    // gmem load mapping
    const int a_r = tid >> 2;            // 0..63  (rows a_r, a_r+64)
    const int a_c = (tid & 3) * 4;       // 0,4,8,12
    const int b_r = tid >> 5;            // 0..7   (rows b_r, b_r+8)
    const int b_c = (tid & 31) * 4;      // 0..124

    const float* Ap = A + (row0 + a_r) * K + a_c;
    const float* Bp = B + (long)b_r * N + col0 + b_c;

    float acc[2][8][4];
    #pragma unroll
    for (int mt = 0; mt < 2; mt++)
        #pragma unroll
        for (int nt = 0; nt < 8; nt++)
            #pragma unroll
            for (int i = 0; i < 4; i++) acc[mt][nt][i] = 0.f;

    // prefetch tile 0
    float4 pa0 = *(const float4*)(Ap);
    float4 pa1 = *(const float4*)(Ap + (long)64 * K);
    float4 pb0 = *(const float4*)(Bp);
    float4 pb1 = *(const float4*)(Bp + (long)8 * N);

    for (int k0 = 0; k0 < K; k0 += 16) {
        __syncthreads();
        // store (transposed A, direct B), converting to tf32 bits
        As[a_c + 0][a_r] = tfbits(pa0.x);
        As[a_c + 1][a_r] = tfbits(pa0.y);
        As[a_c + 2][a_r] = tfbits(pa0.z);
        As[a_c + 3][a_r] = tfbits(pa0.w);
        As[a_c + 0][a_r + 64] = tfbits(pa1.x);
        As[a_c + 1][a_r + 64] = tfbits(pa1.y);
        As[a_c + 2][a_r + 64] = tfbits(pa1.z);
        As[a_c + 3][a_r + 64] = tfbits(pa1.w);
        float4 t0, t1;
        t0.x = tfbits(pb0.x); t0.y = tfbits(pb0.y);
        t0.z = tfbits(pb0.z); t0.w = tfbits(pb0.w);
        t1.x = tfbits(pb1.x); t1.y = tfbits(pb1.y);
        t1.z = tfbits(pb1.z); t1.w = tfbits(pb1.w);
        *(float4*)&Bs[b_r][b_c]     = t0;
        *(float4*)&Bs[b_r + 8][b_c] = t1;
        __syncthreads();

        if (k0 + 16 < K) {
            pa0 = *(const float4*)(Ap + k0 + 16);
            pa1 = *(const float4*)(Ap + (long)64 * K + k0 + 16);
            pb0 = *(const float4*)(Bp + (long)(k0 + 16) * N);
            pb1 = *(const float4*)(Bp + (long)(k0 + 24) * N);
        }

        #pragma unroll
        for (int ks = 0; ks < 2; ks++) {
            const int kk = ks * 8;
            uint32_t af[2][4];
            #pragma unroll
            for (int mt = 0; mt < 2; mt++) {
                int m = wm * 32 + mt * 16 + lq;
                af[mt][0] = __float_as_uint(As[kk + lr][m]);
                af[mt][1] = __float_as_uint(As[kk + lr][m + 8]);
                af[mt][2] = __float_as_uint(As[kk + lr + 4][m]);
                af[mt][3] = __float_as_uint(As[kk + lr + 4][m + 8]);
            }
            uint32_t bf[8][2];
            #pragma unroll
            for (int nt = 0; nt < 8; nt++) {
                int n = wn * 64 + nt * 8 + lq;
                bf[nt][0] = __float_as_uint(Bs[kk + lr][n]);
                bf[nt][1] = __float_as_uint(Bs[kk + lr + 4][n]);
            }
            #pragma unroll
            for (int mt = 0; mt < 2; mt++)
                #pragma unroll
                for (int nt = 0; nt < 8; nt++)
                    mma_tf32(acc[mt][nt], af[mt], bf[nt]);
        }
    }

    // epilogue
    #pragma unroll
    for (int mt = 0; mt < 2; mt++) {
        long r0 = row0 + wm * 32 + mt * 16 + lq;
        #pragma unroll
        for (int nt = 0; nt < 8; nt++) {
            long c = col0 + wn * 64 + nt * 8 + 2 * lr;
            float bx = 0.f, by = 0.f;
            if (bias) { bx = bias[c]; by = bias[c + 1]; }
            float2 v0, v1;
            v0.x = acc[mt][nt][0] + bx; v0.y = acc[mt][nt][1] + by;
            v1.x = acc[mt][nt][2] + bx; v1.y = acc[mt][nt][3] + by;
            *(float2*)(C + r0 * N + c)       = v0;
            *(float2*)(C + (r0 + 8) * N + c) = v1;
        }
    }
}

// ---------------------------------------------------------------------------
// tf32 tensor-core flash attention. CTA = 64 q-rows of one (b,h), 4 warps
// (128 threads). Warp w owns q-rows [w*16, w*16+16). Key tiles of 64.
// Q pre-scaled by SCALE*LOG2E; softmax in exp2 domain on accumulator frags.
// smem: QPs (Q, reused as P) [64][68], Ks [64][68], Vs [64][72].
// ---------------------------------------------------------------------------
#define QK_S 68
#define V_S  72
#define FA_SMEM ((2 * 64 * QK_S + 64 * V_S) * 4)

__global__ void __launch_bounds__(128) flash_attn_tf32(
    const float* __restrict__ qkv, float* __restrict__ out)
{
    extern __shared__ float sm[];
    float (*QPs)[QK_S] = (float(*)[QK_S])(sm);
    float (*Ks)[QK_S]  = (float(*)[QK_S])(sm + 64 * QK_S);
    float (*Vs)[V_S]   = (float(*)[V_S])(sm + 2 * 64 * QK_S);

    const int tid  = threadIdx.x;
    const int lane = tid & 31;
    const int wid  = tid >> 5;
    const int lq   = lane >> 2;
    const int lr   = lane & 3;
    const int wr   = wid * 16;

    const int h  = blockIdx.y;
    const int b  = blockIdx.z;
    const int q0 = blockIdx.x * 64;

    const size_t base = (size_t)b * SEQ * QKV_N;
    const float* qb = qkv + base + h * DHEAD;
    const float* kb = qkv + base + DIMQ + h * DHEAD;
    const float* vb = qkv + base + 2 * DIMQ + h * DHEAD;

    const float qscale = SCALE_A * LOG2E;

    // load Q (scaled, tf32) into QPs
    {
        const int r  = tid >> 4;           // 0..7
        const int c4 = (tid & 15) << 2;    // 0..60
        #pragma unroll
        for (int it = 0; it < 8; it++) {
            int row = r + it * 8;
            float4 v = *(const float4*)(qb + (size_t)(q0 + row) * QKV_N + c4);
            QPs[row][c4 + 0] = tfbits(v.x * qscale);
            QPs[row][c4 + 1] = tfbits(v.y * qscale);
            QPs[row][c4 + 2] = tfbits(v.z * qscale);
            QPs[row][c4 + 3] = tfbits(v.w * qscale);
        }
    }
    __syncthreads();

    // preload Q fragments (8 k-steps x 4 regs)
    uint32_t qf[8][4];
    {
        const int m = wr + lq;
        #pragma unroll
        for (int kk = 0; kk < 8; kk++) {
            qf[kk][0] = __float_as_uint(QPs[m][kk * 8 + lr]);
            qf[kk][1] = __float_as_uint(QPs[m + 8][kk * 8 + lr]);
            qf[kk][2] = __float_as_uint(QPs[m][kk * 8 + lr + 4]);
            qf[kk][3] = __float_as_uint(QPs[m + 8][kk * 8 + lr + 4]);
        }
    }
    __syncthreads();   // QPs now reusable as P buffer

    float o[8][4];
    #pragma unroll
    for (int nt = 0; nt < 8; nt++)
        #pragma unroll
        for (int i = 0; i < 4; i++) o[nt][i] = 0.f;
    float mi_lo = -1e30f, mi_hi = -1e30f, li_lo = 0.f, li_hi = 0.f;

    const int ld_r  = tid >> 4;
    const int ld_c4 = (tid & 15) << 2;

    for (int kt = 0; kt < SEQ; kt += 64) {
        // load K,V tile -> smem (tf32)
        #pragma unroll
        for (int it = 0; it < 8; it++) {
            int row = ld_r + it * 8;
            float4 kv = *(const float4*)(kb + (size_t)(kt + row) * QKV_N + ld_c4);
            Ks[row][ld_c4 + 0] = tfbits(kv.x);
            Ks[row][ld_c4 + 1] = tfbits(kv.y);
            Ks[row][ld_c4 + 2] = tfbits(kv.z);
            Ks[row][ld_c4 + 3] = tfbits(kv.w);
            float4 vv = *(const float4*)(vb + (size_t)(kt + row) * QKV_N + ld_c4);
            Vs[row][ld_c4 + 0] = tfbits(vv.x);
            Vs[row][ld_c4 + 1] = tfbits(vv.y);
            Vs[row][ld_c4 + 2] = tfbits(vv.z);
            Vs[row][ld_c4 + 3] = tfbits(vv.w);
        }
        __syncthreads();

        // S = Q K^T (already in exp2 domain scale)
        float c[8][4];
        #pragma unroll
        for (int nt = 0; nt < 8; nt++)
            #pragma unroll
            for (int i = 0; i < 4; i++) c[nt][i] = 0.f;

        #pragma unroll
        for (int kk = 0; kk < 8; kk++) {
            uint32_t bf[8][2];
            #pragma unroll
            for (int nt = 0; nt < 8; nt++) {
                int n = nt * 8 + lq;
                bf[nt][0] = __float_as_uint(Ks[n][kk * 8 + lr]);
                bf[nt][1] = __float_as_uint(Ks[n][kk * 8 + lr + 4]);
            }
            #pragma unroll
            for (int nt = 0; nt < 8; nt++)
                mma_tf32(c[nt], qf[kk], bf[nt]);
        }

        // online softmax on fragments (rows lq and lq+8 of this warp's m16)
        float mlo = -1e30f, mhi = -1e30f;
        #pragma unroll
        for (int nt = 0; nt < 8; nt++) {
            mlo = fmaxf(mlo, fmaxf(c[nt][0], c[nt][1]));
            mhi = fmaxf(mhi, fmaxf(c[nt][2], c[nt][3]));
        }
        mlo = fmaxf(mlo, __shfl_xor_sync(0xffffffffu, mlo, 1));
        mlo = fmaxf(mlo, __shfl_xor_sync(0xffffffffu, mlo, 2));
        mhi = fmaxf(mhi, __shfl_xor_sync(0xffffffffu, mhi, 1));
        mhi = fmaxf(mhi, __shfl_xor_sync(0xffffffffu, mhi, 2));

        float mn_lo = fmaxf(mi_lo, mlo);
        float mn_hi = fmaxf(mi_hi, mhi);
        float corr_lo = exp2f(mi_lo - mn_lo);
        float corr_hi = exp2f(mi_hi - mn_hi);
        mi_lo = mn_lo; mi_hi = mn_hi;

        float rs_lo = 0.f, rs_hi = 0.f;
        #pragma unroll
        for (int nt = 0; nt < 8; nt++) {
            c[nt][0] = exp2f(c[nt][0] - mn_lo);
            c[nt][1] = exp2f(c[nt][1] - mn_lo);
            c[nt][2] = exp2f(c[nt][2] - mn_hi);
            c[nt][3] = exp2f(c[nt][3] - mn_hi);
            rs_lo += c[nt][0] + c[nt][1];
            rs_hi += c[nt][2] + c[nt][3];
        }
        rs_lo += __shfl_xor_sync(0xffffffffu, rs_lo, 1);
        rs_lo += __shfl_xor_sync(0xffffffffu, rs_lo, 2);
        rs_hi += __shfl_xor_sync(0xffffffffu, rs_hi, 1);
        rs_hi += __shfl_xor_sync(0xffffffffu, rs_hi, 2);

        li_lo = li_lo * corr_lo + rs_lo;
        li_hi = li_hi * corr_hi + rs_hi;

        // rescale O, store P (tf32) into QPs
        #pragma unroll
        for (int nt = 0; nt < 8; nt++) {
            o[nt][0] *= corr_lo; o[nt][1] *= corr_lo;
            o[nt][2] *= corr_hi; o[nt][3] *= corr_hi;
            int col = nt * 8 + 2 * lr;
            QPs[wr + lq][col]     = tfbits(c[nt][0]);
            QPs[wr + lq][col + 1] = tfbits(c[nt][1]);
            QPs[wr + lq + 8][col]     = tfbits(c[nt][2]);
            QPs[wr + lq + 8][col + 1] = tfbits(c[nt][3]);
        }
        __syncthreads();

        // O += P @ V
        #pragma unroll
        for (int kk = 0; kk < 8; kk++) {
            uint32_t ap[4];
            const int m = wr + lq;
            ap[0] = __float_as_uint(QPs[m][kk * 8 + lr]);
            ap[1] = __float_as_uint(QPs[m + 8][kk * 8 + lr]);
            ap[2] = __float_as_uint(QPs[m][kk * 8 + lr + 4]);
            ap[3] = __float_as_uint(QPs[m + 8][kk * 8 + lr + 4]);
            #pragma unroll
            for (int nt = 0; nt < 8; nt++) {
                uint32_t bf[2];
                bf[0] = __float_as_uint(Vs[kk * 8 + lr][nt * 8 + lq]);
                bf[1] = __float_as_uint(Vs[kk * 8 + lr + 4][nt * 8 + lq]);
                mma_tf32(o[nt], ap, bf);
            }
        }
        __syncthreads();   // protect Ks/Vs/QPs for next iteration
    }

    // epilogue: normalize, write to (b, n, h*64+d)
    const float inv_lo = 1.f / li_lo;
    const float inv_hi = 1.f / li_hi;
    float* ob = out + ((size_t)b * SEQ + q0) * DIMQ + h * DHEAD;
    #pragma unroll
    for (int nt = 0; nt < 8; nt++) {
        int col = nt * 8 + 2 * lr;
        int m = wr + lq;
        float2 v0, v1;
        v0.x = o[nt][0] * inv_lo; v0.y = o[nt][1] * inv_lo;
        v1.x = o[nt][2] * inv_hi; v1.y = o[nt][3] * inv_hi;
        *(float2*)(ob + (size_t)m * DIMQ + col)       = v0;
        *(float2*)(ob + (size_t)(m + 8) * DIMQ + col) = v1;
    }
}

// ---------------------------------------------------------------------------
// Launch
// ---------------------------------------------------------------------------
extern "C" void kernel_launch(void* const* d_in, const int* in_sizes, int n_in,
                              void* d_out, int out_size)
{
    const float* x    = (const float*)d_in[0];   // [2,2048,1024]
    const float* Wqkv = (const float*)d_in[1];   // [1024,3072]
    const float* Wout = (const float*)d_in[2];   // [1024,1024]
    const float* bout = (const float*)d_in[3];   // [1024]
    float* out = (float*)d_out;                  // [2,2048,1024]

    float* qkv = nullptr;
    float* att = nullptr;
    cudaGetSymbolAddress((void**)&qkv, g_qkv);
    cudaGetSymbolAddress((void**)&att, g_att);

    // Stage 1: qkv = x @ W_qkv  (4096 x 3072 x 1024)
    {
        dim3 grid(QKV_N / 128, NTOK / 128);
        sgemm_tf32<<<grid, 256>>>(x, Wqkv, nullptr, qkv, NTOK, QKV_N, DIMQ);
    }

    // Stage 2: flash attention
    {
        cudaFuncSetAttribute(flash_attn_tf32,
                             cudaFuncAttributeMaxDynamicSharedMemorySize,
                             FA_SMEM);
        dim3 grid(SEQ / 64, HEADS, BATCH);
        flash_attn_tf32<<<grid, 128, FA_SMEM>>>(qkv, att);
    }

    // Stage 3: out = att @ W_out + b_out  (4096 x 1024 x 1024)
    {
        dim3 grid(DIMQ / 128, NTOK / 128);
        sgemm_tf32<<<grid, 256>>>(att, Wout, bout, out, NTOK, DIMQ, DIMQ);
    }
}